// round 7
// baseline (speedup 1.0000x reference)
#include <cuda_runtime.h>
#include <math.h>

// Problem constants
#define NB        128      // persistent blocks (<= 148 SMs, all resident)
#define NT        256
#define T_STEPS   512
#define BATCH     32
#define IN_SZ     512
#define OUT_SZ    512
#define LHID      512      // per-direction hidden
#define NG        8        // k-groups (one warp each)
#define KPG       192      // K per group (1536/8)
#define KC        32       // k per chunk per group
#define NCH       6        // chunks (192/32)
#define PADK      36       // KC + 4 ; 36*4B = 144 ≡ 16 mod 128 -> conflict-free LDS.128
#define WBUF      (NG * 32 * PADK)             // 9216 floats per buffer
#define HN_BASE   (BATCH * T_STEPS * OUT_SZ)   // 8,388,608

// Packed dual-fp32 FMA (sm_100+): one issue slot = 2 fp32 FMAs, .rn rounding
#define FMA_X2(d, a, b) asm("fma.rn.f32x2 %0, %1, %2, %0;" : "+l"(d) : "l"(a), "l"(b))

// Persistent state (device globals; no allocation allowed)
__device__ float g_hbuf[2][2][2][BATCH][LHID];  // [parity][layer][dir][b][u]
__device__ float g_c[2][2][BATCH][LHID];        // [layer][dir][b][u]
__device__ float g_prev[BATCH][OUT_SZ];
__device__ unsigned int g_count = 0;
__device__ volatile unsigned int g_gen = 0;

__device__ __forceinline__ void grid_sync() {
    __threadfence();           // publish this thread's global writes
    __syncthreads();
    if (threadIdx.x == 0) {
        unsigned gen = g_gen;
        if (atomicAdd(&g_count, 1u) == NB - 1) {
            g_count = 0;
            __threadfence();
            g_gen = gen + 1;
        } else {
            while (g_gen == gen) { }
        }
        __threadfence();
    }
    __syncthreads();
}

__device__ __forceinline__ float sigm(float x) { return 1.0f / (1.0f + expf(-x)); }

__device__ __forceinline__ float x2_sum(unsigned long long a) {
    float lo = __uint_as_float((unsigned)(a & 0xffffffffull));
    float hi = __uint_as_float((unsigned)(a >> 32));
    return lo + hi;
}

// cp.async helpers (LDGSTS, L2-only path: no L1 staleness on recurrent state)
__device__ __forceinline__ void cp_async16(void* smem_dst, const void* gsrc) {
    unsigned saddr = (unsigned)__cvta_generic_to_shared(smem_dst);
    asm volatile("cp.async.cg.shared.global [%0], [%1], 16;\n" :: "r"(saddr), "l"(gsrc));
}
__device__ __forceinline__ void cp_commit() {
    asm volatile("cp.async.commit_group;\n");
}
template <int N> __device__ __forceinline__ void cp_wait() {
    asm volatile("cp.async.wait_group %0;\n" :: "n"(N));
}

// smem layout (floats):
//   layer phase: w_s[2][WBUF] | x_s[2][WBUF] | red[NG*32*33] | tot[32*33] | bias[32]
//                18432        | 18432        | 8448          | 1056      | 32   = 46400
//   FC phase   : hs[32*1028]=32896 | wfc[4096] | fcred[256]   (overlaps w_s/x_s)
#define SMEM_FLOATS 46400
#define SMEM_BYTES  (SMEM_FLOATS * 4)

__global__ void __launch_bounds__(NT, 1)
ae_kernel(const float* __restrict__ x_in,
          const float* __restrict__ W_ih, const float* __restrict__ W_hh,
          const float* __restrict__ b_ih, const float* __restrict__ b_hh,
          const float* __restrict__ W_fc, const float* __restrict__ b_fc,
          float* __restrict__ out)
{
    extern __shared__ float sm[];
    const int tid = threadIdx.x;
    const int bid = blockIdx.x;

    // ---- init state to zero (read at t=0) ----
    {
        float* h0 = &g_hbuf[0][0][0][0][0];
        for (int e = bid * NT + tid; e < 2 * 2 * BATCH * LHID; e += NB * NT) h0[e] = 0.0f;
        float* c0 = &g_c[0][0][0][0];
        for (int e = bid * NT + tid; e < 2 * 2 * BATCH * LHID; e += NB * NT) c0[e] = 0.0f;
        float* p0 = &g_prev[0][0];
        for (int e = bid * NT + tid; e < BATCH * OUT_SZ; e += NB * NT) p0[e] = 0.0f;
    }
    grid_sync();

    // layer-phase block mapping: 128 blocks = 2 dirs x 64 unit-groups of 8 units
    const int d    = bid >> 6;
    const int u0   = (bid & 63) << 3;
    const int grp  = tid >> 5;        // k-group == warp id, 0..7
    const int t32  = tid & 31;        // lane
    const int trow4 = t32 >> 3;       // 0..3 : owns rows trow4*8 .. trow4*8+7
    const int tcol  = t32 & 7;        // 0..7 : owns cols tcol, tcol+8, +16, +24

    float* w_s    = sm;                    // 2 * WBUF = 18432
    float* x_s    = sm + 2 * WBUF;         // 18432
    float* red    = sm + 4 * WBUF;         // NG*32*33 = 8448
    float* tot    = red + NG * 32 * 33;    // 1056
    float* bias_s = tot + 32 * 33;         // 32
    float* hs     = sm;                    // FC: 32*1028 = 32896
    float* wfc_s  = sm + 32 * 1028;        // FC: 4096
    float* fcred  = wfc_s + 4096;          // FC: 256

    for (int t = 0; t < T_STEPS; ++t) {
        const int rp = t & 1;        // read parity of recurrent h
        const int wp = rp ^ 1;       // write parity

        for (int l = 0; l < 2; ++l) {
            // preload combined bias for this block's 32 gate rows
            if (tid < 32) {
                int grow = ((tid >> 3) << 9) + u0 + (tid & 7);
                int bo = (l * 2 + d) * 2048 + grow;
                bias_s[tid] = b_ih[bo] + b_hh[bo];
            }
            const float* wih_base = W_ih + (size_t)(l * 2 + d) * 2048 * 1024;
            const float* whh_base = W_hh + (size_t)(l * 2 + d) * 2048 * 512;

            // ---- staging lambda (cp.async of one chunk into a buffer pair) ----
            auto stage = [&](int ch, float* wbuf, float* xbuf) {
                const int k0 = grp * KPG + ch * KC;   // 32-aligned, never straddles regions
                // weights: 32 rows x 32 k for this group -> 256 float4, 8 per lane
                #pragma unroll
                for (int p = 0; p < 8; ++p) {
                    int idx = p * 32 + t32;
                    int r = idx >> 3, kq4 = idx & 7;
                    int grow = ((r >> 3) << 9) + u0 + (r & 7);
                    const float* src = (k0 < 1024)
                        ? wih_base + (size_t)grow * 1024 + k0 + kq4 * 4
                        : whh_base + (size_t)grow * 512 + (k0 - 1024) + kq4 * 4;
                    cp_async16(&wbuf[(grp * 32 + r) * PADK + kq4 * 4], src);
                }
                // activations: 32 batch x 32 k
                #pragma unroll
                for (int p = 0; p < 8; ++p) {
                    int idx = p * 32 + t32;
                    int c = idx >> 3, kq4 = idx & 7;
                    int k = k0 + kq4 * 4;
                    const float* src;
                    if (l == 0) {
                        if (k < 512)        src = x_in + ((size_t)c * T_STEPS + t) * IN_SZ + k;
                        else if (k < 1024)  src = &g_prev[c][k - 512];
                        else                src = &g_hbuf[rp][0][d][c][k - 1024];
                    } else {
                        if (k < 512)        src = &g_hbuf[wp][0][0][c][k];
                        else if (k < 1024)  src = &g_hbuf[wp][0][1][c][k - 512];
                        else                src = &g_hbuf[rp][1][d][c][k - 1024];
                    }
                    cp_async16(&xbuf[(grp * 32 + c) * PADK + kq4 * 4], src);
                }
            };

            // packed f32x2 accumulators: even-k/odd-k partial sums per (i,j)
            unsigned long long acc2[8][4];
            #pragma unroll
            for (int i = 0; i < 8; ++i)
                #pragma unroll
                for (int j = 0; j < 4; ++j) acc2[i][j] = 0ull;

            // prologue: chunk 0 -> buffer 0
            stage(0, w_s, x_s);
            cp_commit();

            for (int ch = 0; ch < NCH; ++ch) {
                if (ch + 1 < NCH) {
                    stage(ch + 1, w_s + ((ch + 1) & 1) * WBUF, x_s + ((ch + 1) & 1) * WBUF);
                    cp_commit();
                    cp_wait<1>();     // chunk ch complete, ch+1 in flight
                } else {
                    cp_wait<0>();
                }
                __syncthreads();

                const float* wb = w_s + (ch & 1) * WBUF;
                const float* xb = x_s + (ch & 1) * WBUF;
                #pragma unroll
                for (int kq = 0; kq < 8; ++kq) {
                    ulonglong2 xv[4];
                    #pragma unroll
                    for (int j = 0; j < 4; ++j)
                        xv[j] = *(const ulonglong2*)&xb[(grp * 32 + tcol + 8 * j) * PADK + kq * 4];
                    #pragma unroll
                    for (int i = 0; i < 8; ++i) {
                        ulonglong2 wv = *(const ulonglong2*)&wb[(grp * 32 + trow4 * 8 + i) * PADK + kq * 4];
                        #pragma unroll
                        for (int j = 0; j < 4; ++j) {
                            FMA_X2(acc2[i][j], wv.x, xv[j].x);
                            FMA_X2(acc2[i][j], wv.y, xv[j].y);
                        }
                    }
                }
                __syncthreads();   // buffer (ch&1) free for reuse at ch+2
            }

            // write 8 k-partials (fold packed halves)
            #pragma unroll
            for (int i = 0; i < 8; ++i)
                #pragma unroll
                for (int j = 0; j < 4; ++j)
                    red[(grp * 32 + trow4 * 8 + i) * 33 + (tcol + 8 * j)] = x2_sum(acc2[i][j]);
            __syncthreads();
            // reduce partials + bias
            for (int e = tid; e < 1024; e += NT) {
                int r = e >> 5, c = e & 31;
                float s = 0.0f;
                #pragma unroll
                for (int g = 0; g < NG; ++g)
                    s += red[(g * 32 + r) * 33 + c];
                tot[r * 33 + c] = s + bias_s[r];
            }
            __syncthreads();
            // elementwise LSTM cell update: 256 threads = 32 batch x 8 units
            {
                int c = tid >> 3, j = tid & 7;
                float gi = tot[(0 * 8 + j) * 33 + c];
                float gf = tot[(1 * 8 + j) * 33 + c];
                float gg = tot[(2 * 8 + j) * 33 + c];
                float go = tot[(3 * 8 + j) * 33 + c];
                float cold = g_c[l][d][c][u0 + j];
                float cn = sigm(gf) * cold + sigm(gi) * tanhf(gg);
                float hn = sigm(go) * tanhf(cn);
                g_c[l][d][c][u0 + j] = cn;
                g_hbuf[wp][l][d][c][u0 + j] = hn;
            }
            grid_sync();
        }

        // ---- FC phase: pred = h1cat @ W_fc^T + b_fc ----
        {
            // stage h1cat [32 x 1024] and this block's 4 W_fc rows via cp.async
            #pragma unroll 8
            for (int p = 0; p < 32; ++p) {
                int idx = p * 256 + tid;           // 8192 float4
                int c = idx >> 8, kq = idx & 255;
                int k = kq * 4;
                const float* src = (k < 512) ? &g_hbuf[wp][1][0][c][k]
                                             : &g_hbuf[wp][1][1][c][k - 512];
                cp_async16(&hs[c * 1028 + k], src);
            }
            #pragma unroll
            for (int p = 0; p < 4; ++p) {
                int i2 = p * 256 + tid;            // 1024 float4
                cp_async16(&wfc_s[i2 * 4], W_fc + ((size_t)(bid << 2)) * 1024 + i2 * 4);
            }
            cp_commit();
            cp_wait<0>();
            __syncthreads();

            const int o0 = bid << 2;               // 4 output rows per block
            const int kh = tid >> 7, t2 = tid & 127;
            const int ol = t2 >> 5, c = t2 & 31;
            unsigned long long a2 = 0ull;
            const float* wrow = wfc_s + ol * 1024 + kh * 512;
            const float* xrow = hs + c * 1028 + kh * 512;
            #pragma unroll 8
            for (int q = 0; q < 128; ++q) {
                ulonglong2 wv = *(const ulonglong2*)(wrow + q * 4);
                ulonglong2 xv = *(const ulonglong2*)(xrow + q * 4);
                FMA_X2(a2, wv.x, xv.x);
                FMA_X2(a2, wv.y, xv.y);
            }
            fcred[kh * 128 + t2] = x2_sum(a2);
            __syncthreads();
            if (tid < 128) {
                int c2 = tid >> 2, oo = tid & 3;
                int idx = oo * 32 + c2;
                float v = fcred[idx] + fcred[128 + idx] + b_fc[o0 + oo];
                out[((size_t)c2 * T_STEPS + t) * OUT_SZ + o0 + oo] = v;
                g_prev[c2][o0 + oo] = v;
            }
            grid_sync();
        }
    }

    // ---- final h_n, c_n (last write parity = T&1 = 0) ----
    {
        const float* hsrc = &g_hbuf[0][0][0][0][0];   // [l][d][b][u] flat = h_n layout
        const float* csrc = &g_c[0][0][0][0];
        for (int e = bid * NT + tid; e < 2 * 2 * BATCH * LHID; e += NB * NT) {
            out[HN_BASE + e] = hsrc[e];
            out[HN_BASE + 65536 + e] = csrc[e];
        }
    }
}

extern "C" void kernel_launch(void* const* d_in, const int* in_sizes, int n_in,
                              void* d_out, int out_size) {
    const float* input_seq = (const float*)d_in[0];
    // d_in[1] = input_lengths (all == T, unused by the reference path)
    const float* W_ih = (const float*)d_in[2];
    const float* W_hh = (const float*)d_in[3];
    const float* b_ih = (const float*)d_in[4];
    const float* b_hh = (const float*)d_in[5];
    const float* W_fc = (const float*)d_in[6];
    const float* b_fc = (const float*)d_in[7];
    float* out = (float*)d_out;

    cudaFuncSetAttribute(ae_kernel, cudaFuncAttributeMaxDynamicSharedMemorySize, SMEM_BYTES);
    ae_kernel<<<NB, NT, SMEM_BYTES>>>(input_seq, W_ih, W_hh, b_ih, b_hh, W_fc, b_fc, out);
}

// round 8
// speedup vs baseline: 1.2654x; 1.2654x over previous
#include <cuda_runtime.h>
#include <math.h>

// Problem constants
#define NB        128      // persistent blocks (<= 148 SMs, all resident)
#define NT        512      // 16 warps: 8 k-groups x 2 batch-halves
#define T_STEPS   512
#define BATCH     32
#define IN_SZ     512
#define OUT_SZ    512
#define LHID      512      // per-direction hidden
#define NG        8        // k-groups
#define KPG       192      // K per group (1536/8)
#define KC        32       // k per chunk per group
#define NCH       6        // chunks (192/32)
#define PADK      36       // KC + 4 ; row stride 144B (16-aligned, conflict-free LDS.128)
#define WBUF      (NG * 32 * PADK)             // 9216 floats per buffer
#define HN_BASE   (BATCH * T_STEPS * OUT_SZ)   // 8,388,608

// Packed dual-fp32 FMA (sm_100+): one instruction = 2 fp32 FMAs, .rn rounding
#define FMA_X2(d, a, b) asm("fma.rn.f32x2 %0, %1, %2, %0;" : "+l"(d) : "l"(a), "l"(b))

// Persistent state (device globals; no allocation allowed)
__device__ float g_hbuf[2][2][2][BATCH][LHID];  // [parity][layer][dir][b][u]
__device__ float g_c[2][2][BATCH][LHID];        // [layer][dir][b][u]
__device__ float g_prev[BATCH][OUT_SZ];
__device__ unsigned int g_count = 0;
__device__ volatile unsigned int g_gen = 0;

__device__ __forceinline__ void grid_sync() {
    __threadfence();           // publish this thread's global writes
    __syncthreads();
    if (threadIdx.x == 0) {
        unsigned gen = g_gen;
        if (atomicAdd(&g_count, 1u) == NB - 1) {
            g_count = 0;
            __threadfence();
            g_gen = gen + 1;
        } else {
            while (g_gen == gen) { }
        }
        __threadfence();
    }
    __syncthreads();
}

__device__ __forceinline__ float sigm(float x) { return 1.0f / (1.0f + expf(-x)); }

__device__ __forceinline__ float x2_sum(unsigned long long a) {
    float lo = __uint_as_float((unsigned)(a & 0xffffffffull));
    float hi = __uint_as_float((unsigned)(a >> 32));
    return lo + hi;
}

// cp.async helpers (LDGSTS, L2-only path: no L1 staleness on recurrent state)
__device__ __forceinline__ void cp_async16(void* smem_dst, const void* gsrc) {
    unsigned saddr = (unsigned)__cvta_generic_to_shared(smem_dst);
    asm volatile("cp.async.cg.shared.global [%0], [%1], 16;\n" :: "r"(saddr), "l"(gsrc));
}
__device__ __forceinline__ void cp_commit() {
    asm volatile("cp.async.commit_group;\n");
}
template <int N> __device__ __forceinline__ void cp_wait() {
    asm volatile("cp.async.wait_group %0;\n" :: "n"(N));
}

// smem layout (floats):
//   layer phase: w_s[2][WBUF] | x_s[2][WBUF] | red[NG*32*33] | tot[32*33] | bias[32]
//                18432        | 18432        | 8448          | 1056      | 32   = 46400
//   FC phase   : hs[32*1028]=32896 | wfc[4096] | fcred[512]   (overlaps w_s/x_s)
#define SMEM_FLOATS 46400
#define SMEM_BYTES  (SMEM_FLOATS * 4)

__global__ void __launch_bounds__(NT, 1)
ae_kernel(const float* __restrict__ x_in,
          const float* __restrict__ W_ih, const float* __restrict__ W_hh,
          const float* __restrict__ b_ih, const float* __restrict__ b_hh,
          const float* __restrict__ W_fc, const float* __restrict__ b_fc,
          float* __restrict__ out)
{
    extern __shared__ float sm[];
    const int tid = threadIdx.x;
    const int bid = blockIdx.x;

    // ---- init state to zero (read at t=0) ----
    {
        float* h0 = &g_hbuf[0][0][0][0][0];
        for (int e = bid * NT + tid; e < 2 * 2 * BATCH * LHID; e += NB * NT) h0[e] = 0.0f;
        float* c0 = &g_c[0][0][0][0];
        for (int e = bid * NT + tid; e < 2 * 2 * BATCH * LHID; e += NB * NT) c0[e] = 0.0f;
        float* p0 = &g_prev[0][0];
        for (int e = bid * NT + tid; e < BATCH * OUT_SZ; e += NB * NT) p0[e] = 0.0f;
    }
    grid_sync();

    // layer-phase block mapping: 128 blocks = 2 dirs x 64 unit-groups of 8 units
    // thread mapping: 16 warps = 8 k-groups x 2 batch-halves
    const int d     = bid >> 6;
    const int u0    = (bid & 63) << 3;
    const int wid   = tid >> 5;
    const int grp   = wid & 7;        // k-group 0..7
    const int half  = wid >> 3;       // batch half 0/1 (cols half*16 .. half*16+15)
    const int t32   = tid & 31;       // lane
    const int trow4 = t32 >> 3;       // 0..3 : owns rows trow4*8 .. trow4*8+7
    const int tcol  = t32 & 7;        // 0..7 : owns cols half*16 + tcol, +8

    float* w_s    = sm;                    // 2 * WBUF = 18432
    float* x_s    = sm + 2 * WBUF;         // 18432
    float* red    = sm + 4 * WBUF;         // NG*32*33 = 8448
    float* tot    = red + NG * 32 * 33;    // 1056
    float* bias_s = tot + 32 * 33;         // 32
    float* hs     = sm;                    // FC: 32*1028 = 32896
    float* wfc_s  = sm + 32 * 1028;        // FC: 4096
    float* fcred  = wfc_s + 4096;          // FC: 512

    for (int t = 0; t < T_STEPS; ++t) {
        const int rp = t & 1;        // read parity of recurrent h
        const int wp = rp ^ 1;       // write parity

        for (int l = 0; l < 2; ++l) {
            // preload combined bias for this block's 32 gate rows
            if (tid < 32) {
                int grow = ((tid >> 3) << 9) + u0 + (tid & 7);
                int bo = (l * 2 + d) * 2048 + grow;
                bias_s[tid] = b_ih[bo] + b_hh[bo];
            }
            const float* wih_base = W_ih + (size_t)(l * 2 + d) * 2048 * 1024;
            const float* whh_base = W_hh + (size_t)(l * 2 + d) * 2048 * 512;

            // ---- staging: half-0 warps stage weights, half-1 warps stage x ----
            auto stage = [&](int ch, float* wbuf, float* xbuf) {
                const int k0 = grp * KPG + ch * KC;   // 32-aligned, never straddles regions
                if (half == 0) {
                    // weights: 32 rows x 32 k for this group -> 256 float4, 8 per lane
                    #pragma unroll
                    for (int p = 0; p < 8; ++p) {
                        int idx = p * 32 + t32;
                        int r = idx >> 3, kq4 = idx & 7;
                        int grow = ((r >> 3) << 9) + u0 + (r & 7);
                        const float* src = (k0 < 1024)
                            ? wih_base + (size_t)grow * 1024 + k0 + kq4 * 4
                            : whh_base + (size_t)grow * 512 + (k0 - 1024) + kq4 * 4;
                        cp_async16(&wbuf[(grp * 32 + r) * PADK + kq4 * 4], src);
                    }
                } else {
                    // activations: 32 batch x 32 k -> 256 float4, 8 per lane
                    #pragma unroll
                    for (int p = 0; p < 8; ++p) {
                        int idx = p * 32 + t32;
                        int c = idx >> 3, kq4 = idx & 7;
                        int k = k0 + kq4 * 4;
                        const float* src;
                        if (l == 0) {
                            if (k < 512)        src = x_in + ((size_t)c * T_STEPS + t) * IN_SZ + k;
                            else if (k < 1024)  src = &g_prev[c][k - 512];
                            else                src = &g_hbuf[rp][0][d][c][k - 1024];
                        } else {
                            if (k < 512)        src = &g_hbuf[wp][0][0][c][k];
                            else if (k < 1024)  src = &g_hbuf[wp][0][1][c][k - 512];
                            else                src = &g_hbuf[rp][1][d][c][k - 1024];
                        }
                        cp_async16(&xbuf[(grp * 32 + c) * PADK + kq4 * 4], src);
                    }
                }
            };

            // packed f32x2 accumulators: even/odd-k partials, 8 rows x 2 cols
            unsigned long long acc2[8][2];
            #pragma unroll
            for (int i = 0; i < 8; ++i) { acc2[i][0] = 0ull; acc2[i][1] = 0ull; }

            // prologue: chunk 0 -> buffer 0
            stage(0, w_s, x_s);
            cp_commit();

            for (int ch = 0; ch < NCH; ++ch) {
                if (ch + 1 < NCH) {
                    stage(ch + 1, w_s + ((ch + 1) & 1) * WBUF, x_s + ((ch + 1) & 1) * WBUF);
                    cp_commit();
                    cp_wait<1>();     // chunk ch complete, ch+1 in flight
                } else {
                    cp_wait<0>();
                }
                __syncthreads();

                const float* wb = w_s + (ch & 1) * WBUF;
                const float* xb = x_s + (ch & 1) * WBUF;
                #pragma unroll
                for (int kq = 0; kq < 8; ++kq) {
                    ulonglong2 xv[2];
                    #pragma unroll
                    for (int j = 0; j < 2; ++j)
                        xv[j] = *(const ulonglong2*)
                            &xb[(grp * 32 + half * 16 + tcol + 8 * j) * PADK + kq * 4];
                    #pragma unroll
                    for (int i = 0; i < 8; ++i) {
                        ulonglong2 wv = *(const ulonglong2*)
                            &wb[(grp * 32 + trow4 * 8 + i) * PADK + kq * 4];
                        #pragma unroll
                        for (int j = 0; j < 2; ++j) {
                            FMA_X2(acc2[i][j], wv.x, xv[j].x);
                            FMA_X2(acc2[i][j], wv.y, xv[j].y);
                        }
                    }
                }
                __syncthreads();   // buffer (ch&1) free for reuse at ch+2
            }

            // write 8 k-partials (fold packed halves)
            #pragma unroll
            for (int i = 0; i < 8; ++i)
                #pragma unroll
                for (int j = 0; j < 2; ++j)
                    red[(grp * 32 + trow4 * 8 + i) * 33 + (half * 16 + tcol + 8 * j)]
                        = x2_sum(acc2[i][j]);
            __syncthreads();
            // reduce partials + bias
            for (int e = tid; e < 1024; e += NT) {
                int r = e >> 5, c = e & 31;
                float s = 0.0f;
                #pragma unroll
                for (int g = 0; g < NG; ++g)
                    s += red[(g * 32 + r) * 33 + c];
                tot[r * 33 + c] = s + bias_s[r];
            }
            __syncthreads();
            // elementwise LSTM cell update: 256 threads = 32 batch x 8 units
            if (tid < 256) {
                int c = tid >> 3, j = tid & 7;
                float gi = tot[(0 * 8 + j) * 33 + c];
                float gf = tot[(1 * 8 + j) * 33 + c];
                float gg = tot[(2 * 8 + j) * 33 + c];
                float go = tot[(3 * 8 + j) * 33 + c];
                float cold = g_c[l][d][c][u0 + j];
                float cn = sigm(gf) * cold + sigm(gi) * tanhf(gg);
                float hn = sigm(go) * tanhf(cn);
                g_c[l][d][c][u0 + j] = cn;
                g_hbuf[wp][l][d][c][u0 + j] = hn;
            }
            grid_sync();
        }

        // ---- FC phase: pred = h1cat @ W_fc^T + b_fc ----
        {
            // stage h1cat [32 x 1024] and this block's 4 W_fc rows via cp.async
            #pragma unroll
            for (int p = 0; p < 16; ++p) {
                int idx = p * NT + tid;            // 8192 float4
                int c = idx >> 8, kq = idx & 255;
                int k = kq * 4;
                const float* src = (k < 512) ? &g_hbuf[wp][1][0][c][k]
                                             : &g_hbuf[wp][1][1][c][k - 512];
                cp_async16(&hs[c * 1028 + k], src);
            }
            #pragma unroll
            for (int p = 0; p < 2; ++p) {
                int i2 = p * NT + tid;             // 1024 float4
                cp_async16(&wfc_s[i2 * 4], W_fc + ((size_t)(bid << 2)) * 1024 + i2 * 4);
            }
            cp_commit();
            cp_wait<0>();
            __syncthreads();

            const int o0 = bid << 2;               // 4 output rows per block
            const int kh = tid >> 7, t2 = tid & 127;   // kh: 0..3 k-quarters of 256
            const int ol = t2 >> 5, c = t2 & 31;
            unsigned long long a2 = 0ull;
            const float* wrow = wfc_s + ol * 1024 + kh * 256;
            const float* xrow = hs + c * 1028 + kh * 256;
            #pragma unroll 8
            for (int q = 0; q < 64; ++q) {
                ulonglong2 wv = *(const ulonglong2*)(wrow + q * 4);
                ulonglong2 xv = *(const ulonglong2*)(xrow + q * 4);
                FMA_X2(a2, wv.x, xv.x);
                FMA_X2(a2, wv.y, xv.y);
            }
            fcred[kh * 128 + t2] = x2_sum(a2);
            __syncthreads();
            if (tid < 128) {
                int c2 = tid >> 2, oo = tid & 3;
                int idx = oo * 32 + c2;
                float v = fcred[idx] + fcred[128 + idx] + fcred[256 + idx] + fcred[384 + idx]
                        + b_fc[o0 + oo];
                out[((size_t)c2 * T_STEPS + t) * OUT_SZ + o0 + oo] = v;
                g_prev[c2][o0 + oo] = v;
            }
            grid_sync();
        }
    }

    // ---- final h_n, c_n (last write parity = T&1 = 0) ----
    {
        const float* hsrc = &g_hbuf[0][0][0][0][0];   // [l][d][b][u] flat = h_n layout
        const float* csrc = &g_c[0][0][0][0];
        for (int e = bid * NT + tid; e < 2 * 2 * BATCH * LHID; e += NB * NT) {
            out[HN_BASE + e] = hsrc[e];
            out[HN_BASE + 65536 + e] = csrc[e];
        }
    }
}

extern "C" void kernel_launch(void* const* d_in, const int* in_sizes, int n_in,
                              void* d_out, int out_size) {
    const float* input_seq = (const float*)d_in[0];
    // d_in[1] = input_lengths (all == T, unused by the reference path)
    const float* W_ih = (const float*)d_in[2];
    const float* W_hh = (const float*)d_in[3];
    const float* b_ih = (const float*)d_in[4];
    const float* b_hh = (const float*)d_in[5];
    const float* W_fc = (const float*)d_in[6];
    const float* b_fc = (const float*)d_in[7];
    float* out = (float*)d_out;

    cudaFuncSetAttribute(ae_kernel, cudaFuncAttributeMaxDynamicSharedMemorySize, SMEM_BYTES);
    ae_kernel<<<NB, NT, SMEM_BYTES>>>(input_seq, W_ih, W_hh, b_ih, b_hh, W_fc, b_fc, out);
}

// round 9
// speedup vs baseline: 1.6919x; 1.3370x over previous
#include <cuda_runtime.h>
#include <math.h>

// Problem constants
#define NB        128      // persistent blocks (<= 148 SMs, all resident)
#define NT        256      // 8 warps = 8 k-groups (warp-private pipelines)
#define T_STEPS   512
#define BATCH     32
#define IN_SZ     512
#define OUT_SZ    512
#define LHID      512
#define NG        8        // k-groups (one warp each)
#define KPG       192      // K per group (1536/8)
#define KC        32       // k per chunk per group
#define NCH       6        // chunks (192/32)
#define PADK      36       // row stride 144B
#define SLICE     (32 * PADK)                  // 1152 floats: per-warp slice in a buffer
#define BUFSZ     (NG * SLICE)                 // 9216 floats per buffer
#define HN_BASE   (BATCH * T_STEPS * OUT_SZ)   // 8,388,608

// Persistent state (device globals; no allocation allowed)
__device__ float g_hbuf[2][2][2][BATCH][LHID];  // [parity][layer][dir][b][u]
__device__ float g_c[2][2][BATCH][LHID];        // [layer][dir][b][u]
__device__ float g_prev[BATCH][OUT_SZ];
__device__ unsigned int g_count = 0;
__device__ volatile unsigned int g_gen = 0;

__device__ __forceinline__ void grid_sync() {
    __threadfence();
    __syncthreads();
    if (threadIdx.x == 0) {
        unsigned gen = g_gen;
        if (atomicAdd(&g_count, 1u) == NB - 1) {
            g_count = 0;
            __threadfence();
            g_gen = gen + 1;
        } else {
            while (g_gen == gen) { }
        }
        __threadfence();
    }
    __syncthreads();
}

__device__ __forceinline__ float sigm(float x) { return 1.0f / (1.0f + expf(-x)); }

// cp.async (L2-only .cg path: coherent with other SMs' writes, no L1 staleness)
__device__ __forceinline__ void cp_async16(void* smem_dst, const void* gsrc) {
    unsigned saddr = (unsigned)__cvta_generic_to_shared(smem_dst);
    asm volatile("cp.async.cg.shared.global [%0], [%1], 16;\n" :: "r"(saddr), "l"(gsrc));
}
__device__ __forceinline__ void cp_commit() {
    asm volatile("cp.async.commit_group;\n");
}
template <int N> __device__ __forceinline__ void cp_wait() {
    asm volatile("cp.async.wait_group %0;\n" :: "n"(N));
}

// smem: 3 w-buffers [0..27648) | 3 x-buffers [27648..55296)
// overlays: red -> x-buf2 region [46080..54528)
//           FC: hs [0..32896) | wfc [32896..36992) | fcred [36992..37248)
#define SMEM_FLOATS (6 * BUFSZ)   // 55296
#define SMEM_BYTES  (SMEM_FLOATS * 4)

__global__ void __launch_bounds__(NT, 1)
ae_kernel(const float* __restrict__ x_in,
          const float* __restrict__ W_ih, const float* __restrict__ W_hh,
          const float* __restrict__ b_ih, const float* __restrict__ b_hh,
          const float* __restrict__ W_fc, const float* __restrict__ b_fc,
          float* __restrict__ out)
{
    extern __shared__ float sm[];
    const int tid = threadIdx.x;
    const int bid = blockIdx.x;

    // ---- init state to zero ----
    {
        float* h0 = &g_hbuf[0][0][0][0][0];
        for (int e = bid * NT + tid; e < 2 * 2 * BATCH * LHID; e += NB * NT) h0[e] = 0.0f;
        float* c0 = &g_c[0][0][0][0];
        for (int e = bid * NT + tid; e < 2 * 2 * BATCH * LHID; e += NB * NT) c0[e] = 0.0f;
        float* p0 = &g_prev[0][0];
        for (int e = bid * NT + tid; e < BATCH * OUT_SZ; e += NB * NT) p0[e] = 0.0f;
    }

    // block mapping: 128 blocks = 2 dirs x 64 unit-groups of 8 units
    const int d     = bid >> 6;
    const int u0    = (bid & 63) << 3;
    const int grp   = tid >> 5;        // k-group == warp
    const int t32   = tid & 31;
    const int trow4 = t32 >> 3;        // 0..3: rows trow4*8 .. +7
    const int tcol  = t32 & 7;         // 0..7: cols tcol, +8, +16, +24

    float* red   = sm + 5 * BUFSZ;         // 8448 floats (x-buf2 region)
    float* hs    = sm;                     // FC: 32*1028 = 32896
    float* wfc_s = sm + 32 * 1028;         // FC: 4096
    float* fcred = wfc_s + 4096;           // FC: 256

    const float* wih0 = W_ih + (size_t)(0 * 2 + d) * 2048 * 1024;
    const float* whh0 = W_hh + (size_t)(0 * 2 + d) * 2048 * 512;
    const float* wih1 = W_ih + (size_t)(1 * 2 + d) * 2048 * 1024;
    const float* whh1 = W_hh + (size_t)(1 * 2 + d) * 2048 * 512;

    // stage weights of layer l, chunk ch into buffer b (warp-private slice).
    // w-buffer uses XOR slot swizzle: slot = (kq4 + (r>>3)) & 7 -> conflict-free wv LDS.
    auto stage_w = [&](int l, int ch, int b) {
        const int k0 = grp * KPG + ch * KC;
        const float* base; int stride;
        if (k0 < 1024) { base = (l ? wih1 : wih0) + k0;          stride = 1024; }
        else           { base = (l ? whh1 : whh0) + (k0 - 1024); stride = 512;  }
        float* wbuf = sm + b * BUFSZ + grp * SLICE;
        #pragma unroll
        for (int p = 0; p < 8; ++p) {
            int idx = p * 32 + t32;
            int r = idx >> 3, kq4 = idx & 7;
            int grow = ((r >> 3) << 9) + u0 + (r & 7);
            int slot = (kq4 + (r >> 3)) & 7;
            cp_async16(&wbuf[r * PADK + slot * 4], base + (size_t)grow * stride + kq4 * 4);
        }
    };

    // stage activations of layer l, chunk ch (uniform base+stride per chunk)
    auto stage_x = [&](int l, int ch, int b, int t, int rp, int wp) {
        const int k0 = grp * KPG + ch * KC;
        const float* bx; int sx;
        if (l == 0) {
            if (k0 < 512)       { bx = x_in + (size_t)t * IN_SZ + k0;        sx = T_STEPS * IN_SZ; }
            else if (k0 < 1024) { bx = &g_prev[0][k0 - 512];                 sx = OUT_SZ; }
            else                { bx = &g_hbuf[rp][0][d][0][k0 - 1024];      sx = LHID; }
        } else {
            if (k0 < 512)       { bx = &g_hbuf[wp][0][0][0][k0];             sx = LHID; }
            else if (k0 < 1024) { bx = &g_hbuf[wp][0][1][0][k0 - 512];       sx = LHID; }
            else                { bx = &g_hbuf[rp][1][d][0][k0 - 1024];      sx = LHID; }
        }
        float* xbuf = sm + (3 + b) * BUFSZ + grp * SLICE;
        #pragma unroll
        for (int p = 0; p < 8; ++p) {
            int idx = p * 32 + t32;
            int c = idx >> 3, kq4 = idx & 7;
            cp_async16(&xbuf[c * PADK + kq4 * 4], bx + (size_t)c * sx + kq4 * 4);
        }
    };

    // prologue: pre-issue weights for (t=0, l=0) chunks 0,1; then global init sync
    stage_w(0, 0, 0);
    stage_w(0, 1, 1);
    grid_sync();

    for (int t = 0; t < T_STEPS; ++t) {
        const int rp = t & 1;
        const int wp = rp ^ 1;

        for (int l = 0; l < 2; ++l) {
            // entry invariant: w(ch0)->buf0, w(ch1)->buf1 already issued (uncommitted)
            stage_x(l, 0, 0, t, rp, wp); cp_commit();   // G0 = {w0, w1, x0}
            stage_x(l, 1, 1, t, rp, wp); cp_commit();   // G1 = {x1}

            float acc[8][4];
            #pragma unroll
            for (int i = 0; i < 8; ++i)
                #pragma unroll
                for (int j = 0; j < 4; ++j) acc[i][j] = 0.0f;

            #pragma unroll
            for (int ch = 0; ch < NCH; ++ch) {
                if (ch < 4) {
                    stage_w(l, ch + 2, (ch + 2) % 3);
                    stage_x(l, ch + 2, (ch + 2) % 3, t, rp, wp);
                    cp_commit();
                    cp_wait<2>();          // group ch complete
                } else if (ch == 4) {
                    cp_wait<1>();
                } else {
                    cp_wait<0>();
                }
                // warp-private buffers: NO block barrier needed in this loop
                const float* wb = sm + (ch % 3) * BUFSZ + grp * SLICE;
                const float* xb = sm + (3 + ch % 3) * BUFSZ + grp * SLICE;
                #pragma unroll
                for (int kq = 0; kq < 8; ++kq) {
                    float4 xv[4];
                    #pragma unroll
                    for (int j = 0; j < 4; ++j)
                        xv[j] = *(const float4*)&xb[(tcol + 8 * j) * PADK + kq * 4];
                    const int wslot = ((kq + trow4) & 7) * 4;
                    #pragma unroll
                    for (int i = 0; i < 8; ++i) {
                        float4 wv = *(const float4*)&wb[(trow4 * 8 + i) * PADK + wslot];
                        #pragma unroll
                        for (int j = 0; j < 4; ++j) {
                            acc[i][j] += wv.x * xv[j].x;
                            acc[i][j] += wv.y * xv[j].y;
                            acc[i][j] += wv.z * xv[j].z;
                            acc[i][j] += wv.w * xv[j].w;
                        }
                    }
                }
            }

            __syncthreads();   // red overlays x-buf2 (cross-warp) — all computes done
            #pragma unroll
            for (int i = 0; i < 8; ++i)
                #pragma unroll
                for (int j = 0; j < 4; ++j)
                    red[(grp * 32 + trow4 * 8 + i) * 33 + (tcol + 8 * j)] = acc[i][j];
            __syncthreads();

            // cell: direct 8-partial sum + bias from gmem; 256 thr = 32 batch x 8 units
            {
                int c = tid >> 3, j = tid & 7;
                float g4[4];
                #pragma unroll
                for (int gate = 0; gate < 4; ++gate) {
                    int r = gate * 8 + j;
                    float s = 0.0f;
                    #pragma unroll
                    for (int g = 0; g < NG; ++g)
                        s += red[(g * 32 + r) * 33 + c];
                    int bo = (l * 2 + d) * 2048 + (gate << 9) + u0 + j;
                    g4[gate] = s + b_ih[bo] + b_hh[bo];
                }
                float cold = g_c[l][d][c][u0 + j];
                float cn = sigm(g4[1]) * cold + sigm(g4[0]) * tanhf(g4[2]);
                float hn = sigm(g4[3]) * tanhf(cn);
                g_c[l][d][c][u0 + j] = cn;
                g_hbuf[wp][l][d][c][u0 + j] = hn;
            }

            // pre-issue next phase's independent loads before the barrier
            if (l == 0) {
                stage_w(1, 0, 0);
                stage_w(1, 1, 1);
            } else {
                // wfc rows for FC phase (wfc_s overlays dead x-buf0/1 tails)
                #pragma unroll
                for (int p = 0; p < 4; ++p) {
                    int i2 = p * NT + tid;     // 1024 float4
                    cp_async16(&wfc_s[i2 * 4], W_fc + ((size_t)(bid << 2)) * 1024 + i2 * 4);
                }
            }
            grid_sync();
        }

        // ---- FC phase: pred = h1cat @ W_fc^T + b_fc ----
        {
            #pragma unroll 8
            for (int p = 0; p < 32; ++p) {
                int idx = p * NT + tid;        // 8192 float4
                int c = idx >> 8, kq = idx & 255;
                int k = kq * 4;
                const float* src = (k < 512) ? &g_hbuf[wp][1][0][c][k]
                                             : &g_hbuf[wp][1][1][c][k - 512];
                cp_async16(&hs[c * 1028 + k], src);
            }
            cp_commit();                       // bundles the prestaged wfc too
            cp_wait<0>();
            __syncthreads();

            const int o0 = bid << 2;
            const int kh = tid >> 7, t2 = tid & 127;
            const int ol = t2 >> 5, c = t2 & 31;
            float a = 0.0f;
            const float* wrow = wfc_s + ol * 1024 + kh * 512;
            const float* xrow = hs + c * 1028 + kh * 512;
            #pragma unroll 8
            for (int q = 0; q < 128; ++q) {
                float4 wv = *(const float4*)(wrow + q * 4);
                float4 xv = *(const float4*)(xrow + q * 4);
                a += wv.x * xv.x; a += wv.y * xv.y;
                a += wv.z * xv.z; a += wv.w * xv.w;
            }
            fcred[kh * 128 + t2] = a;
            __syncthreads();

            // pre-issue next step's layer-0 weights (hs no longer read)
            if (t + 1 < T_STEPS) {
                stage_w(0, 0, 0);
                stage_w(0, 1, 1);
            }
            if (tid < 128) {
                int c2 = tid >> 2, oo = tid & 3;
                int idx = oo * 32 + c2;
                float v = fcred[idx] + fcred[128 + idx] + b_fc[o0 + oo];
                out[((size_t)c2 * T_STEPS + t) * OUT_SZ + o0 + oo] = v;
                g_prev[c2][o0 + oo] = v;
            }
            grid_sync();
        }
    }

    // ---- final h_n, c_n (last write parity = T&1 = 0); __ldcg for cross-SM data ----
    {
        const float* hsrc = &g_hbuf[0][0][0][0][0];
        const float* csrc = &g_c[0][0][0][0];
        for (int e = bid * NT + tid; e < 2 * 2 * BATCH * LHID; e += NB * NT) {
            out[HN_BASE + e] = __ldcg(&hsrc[e]);
            out[HN_BASE + 65536 + e] = __ldcg(&csrc[e]);
        }
    }
}

extern "C" void kernel_launch(void* const* d_in, const int* in_sizes, int n_in,
                              void* d_out, int out_size) {
    const float* input_seq = (const float*)d_in[0];
    // d_in[1] = input_lengths (all == T, unused by the reference path)
    const float* W_ih = (const float*)d_in[2];
    const float* W_hh = (const float*)d_in[3];
    const float* b_ih = (const float*)d_in[4];
    const float* b_hh = (const float*)d_in[5];
    const float* W_fc = (const float*)d_in[6];
    const float* b_fc = (const float*)d_in[7];
    float* out = (float*)d_out;

    cudaFuncSetAttribute(ae_kernel, cudaFuncAttributeMaxDynamicSharedMemorySize, SMEM_BYTES);
    ae_kernel<<<NB, NT, SMEM_BYTES>>>(input_seq, W_ih, W_hh, b_ih, b_hh, W_fc, b_fc, out);
}